// round 17
// baseline (speedup 1.0000x reference)
#include <cuda_runtime.h>
#include <cuda_bf16.h>
#include <math.h>
#include <stdint.h>

// B=4, S=2048, D=1024, H=16, DK=64 -> M = 8192 tokens.
// Head split reshape(B*H, S, DK) is an identity on the flat buffer.
#define MTOK   8192
#define DMODEL 1024
#define BHEADS 64
#define SEQ    2048
#define DKH    64

// Scratch (device globals; bf16 rounding equals the cvt consumers did anyway)
__device__ __nv_bfloat16 g_qp [MTOK * DMODEL];
__device__ __nv_bfloat16 g_kp [MTOK * DMODEL];
__device__ __nv_bfloat16 g_vp [MTOK * DMODEL];
__device__ __nv_bfloat16 g_ctx[MTOK * DMODEL];
// Pre-converted bf16 inputs and weights
__device__ __nv_bfloat16 g_qin[MTOK * DMODEL];
__device__ __nv_bfloat16 g_kin[MTOK * DMODEL];
__device__ __nv_bfloat16 g_vin[MTOK * DMODEL];
__device__ __nv_bfloat16 g_wq [DMODEL * DMODEL];
__device__ __nv_bfloat16 g_wk [DMODEL * DMODEL];
__device__ __nv_bfloat16 g_wv [DMODEL * DMODEL];
__device__ __nv_bfloat16 g_wo [DMODEL * DMODEL];

// Q pre-scale: 1/sqrt(64) * log2(e)  -> scores land in the exp2 domain.
#define QSCALE 0.18033688011112042f

// ---------------------------------------------------------------------------
// PTX helpers
// ---------------------------------------------------------------------------
__device__ __forceinline__ uint32_t packbf(float lo, float hi) {
    uint32_t r;
    asm("cvt.rn.bf16x2.f32 %0, %1, %2;" : "=r"(r) : "f"(hi), "f"(lo));
    return r;
}

__device__ __forceinline__ float ex2(float x) {
    float r;
    asm("ex2.approx.f32 %0, %1;" : "=f"(r) : "f"(x));
    return r;
}

__device__ __forceinline__ void ldsm4(uint32_t* r, uint32_t saddr) {
    asm volatile("ldmatrix.sync.aligned.m8n8.x4.shared.b16 {%0,%1,%2,%3}, [%4];"
                 : "=r"(r[0]), "=r"(r[1]), "=r"(r[2]), "=r"(r[3]) : "r"(saddr));
}

__device__ __forceinline__ void ldsm4t(uint32_t* r, uint32_t saddr) {
    asm volatile("ldmatrix.sync.aligned.m8n8.x4.trans.shared.b16 {%0,%1,%2,%3}, [%4];"
                 : "=r"(r[0]), "=r"(r[1]), "=r"(r[2]), "=r"(r[3]) : "r"(saddr));
}

__device__ __forceinline__ void mma_bf16(float* c, const uint32_t* a, const uint32_t* b) {
    asm volatile(
        "mma.sync.aligned.m16n8k16.row.col.f32.bf16.bf16.f32 "
        "{%0,%1,%2,%3}, {%4,%5,%6,%7}, {%8,%9}, {%0,%1,%2,%3};"
        : "+f"(c[0]), "+f"(c[1]), "+f"(c[2]), "+f"(c[3])
        : "r"(a[0]), "r"(a[1]), "r"(a[2]), "r"(a[3]), "r"(b[0]), "r"(b[1]));
}

__device__ __forceinline__ void cpasync16(uint32_t smem, const void* gmem) {
    asm volatile("cp.async.cg.shared.global [%0], [%1], 16;" :: "r"(smem), "l"(gmem));
}
#define CP_COMMIT() asm volatile("cp.async.commit_group;")
#define CP_WAIT(N)  asm volatile("cp.async.wait_group %0;" :: "n"(N))

// ---------------------------------------------------------------------------
// fp32 -> bf16 conversion kernels (one-time per launch)
// ---------------------------------------------------------------------------
__global__ __launch_bounds__(256)
void cvt_inputs(const float* __restrict__ a, const float* __restrict__ b,
                const float* __restrict__ c,
                __nv_bfloat16* __restrict__ oa, __nv_bfloat16* __restrict__ ob,
                __nv_bfloat16* __restrict__ oc)
{
    const float* in; __nv_bfloat16* out;
    if (blockIdx.y == 0)      { in = a; out = oa; }
    else if (blockIdx.y == 1) { in = b; out = ob; }
    else                      { in = c; out = oc; }
    const size_t i = ((size_t)blockIdx.x * 256 + threadIdx.x) * 4;
    float4 v = *(const float4*)&in[i];
    uint2 u; u.x = packbf(v.x, v.y); u.y = packbf(v.z, v.w);
    *(uint2*)&out[i] = u;
}

__global__ __launch_bounds__(256)
void cvt_weights(const float* __restrict__ a, const float* __restrict__ b,
                 const float* __restrict__ c, const float* __restrict__ d,
                 __nv_bfloat16* __restrict__ oa, __nv_bfloat16* __restrict__ ob,
                 __nv_bfloat16* __restrict__ oc, __nv_bfloat16* __restrict__ od)
{
    const float* in; __nv_bfloat16* out;
    if (blockIdx.y == 0)      { in = a; out = oa; }
    else if (blockIdx.y == 1) { in = b; out = ob; }
    else if (blockIdx.y == 2) { in = c; out = oc; }
    else                      { in = d; out = od; }
    const size_t i = ((size_t)blockIdx.x * 256 + threadIdx.x) * 4;
    float4 v = *(const float4*)&in[i];
    uint2 u; u.x = packbf(v.x, v.y); u.y = packbf(v.z, v.w);
    *(uint2*)&out[i] = u;
}

// ---------------------------------------------------------------------------
// All-bf16 GEMM body, cp.async 2-stage ring with ONE barrier per stage
// (wait -> sync -> prefetch s+1 -> compute s). Block 128x128, BK=32, 8 warps.
// oscale multiplies (acc + bias) before output (used for Q pre-scaling).
// ---------------------------------------------------------------------------
template<bool RES, bool CBF>
__device__ __forceinline__
void gemm_body(const __nv_bfloat16* __restrict__ X, const __nv_bfloat16* __restrict__ W,
               const float* __restrict__ bias, const float* __restrict__ R,
               void* __restrict__ Cv, int m0, int n0, float oscale)
{
    __shared__ __nv_bfloat16 Xs[2][128 * 40];
    __shared__ __nv_bfloat16 Ws[2][128 * 40];

    const int tid  = threadIdx.x;
    const int lane = tid & 31;
    const int wid  = tid >> 5;
    const int wm   = (wid & 1) * 64;
    const int wn   = (wid >> 1) * 32;

    float acc[4][4][4];
#pragma unroll
    for (int i = 0; i < 4; i++)
#pragma unroll
        for (int j = 0; j < 4; j++)
#pragma unroll
            for (int c = 0; c < 4; c++) acc[i][j][c] = 0.f;

    const uint32_t xs0 = (uint32_t)__cvta_generic_to_shared(&Xs[0][0]);
    const uint32_t ws0 = (uint32_t)__cvta_generic_to_shared(&Ws[0][0]);

    const int c_row = tid >> 2;          // +64 for second chunk
    const int c_col = (tid & 3) * 16;

    auto stage = [&](int K0, int buf) {
        const uint32_t xb = xs0 + (uint32_t)(buf * 128 * 80);
        const uint32_t wb = ws0 + (uint32_t)(buf * 128 * 80);
#pragma unroll
        for (int it = 0; it < 2; it++) {
            const int row = c_row + it * 64;
            cpasync16(xb + (uint32_t)(row * 80 + c_col),
                      (const char*)&X[(size_t)(m0 + row) * DMODEL + K0] + c_col);
            cpasync16(wb + (uint32_t)(row * 80 + c_col),
                      (const char*)&W[(size_t)(n0 + row) * DMODEL + K0] + c_col);
        }
    };

    const int a_row = wm + (lane & 15);
    const int a_byt = 16 * (lane >> 4);
    const int b_row = wn + 8 * (lane >> 4) + (lane & 7);
    const int b_byt = 16 * ((lane >> 3) & 1);

    stage(0, 0);
    CP_COMMIT();

    const int NS = DMODEL / 32;   // 32 stages
    for (int s = 0; s < NS; s++) {
        const int buf = s & 1;
        CP_WAIT(0);
        __syncthreads();
        if (s + 1 < NS) {                 // prefetch overlaps compute of s
            stage((s + 1) * 32, buf ^ 1);
            CP_COMMIT();
        }

        const uint32_t xb = xs0 + (uint32_t)(buf * 128 * 80);
        const uint32_t wb = ws0 + (uint32_t)(buf * 128 * 80);
#pragma unroll
        for (int kk = 0; kk < 32; kk += 16) {
            uint32_t A[4][4], Bf[2][4];
#pragma unroll
            for (int i = 0; i < 4; i++)
                ldsm4(A[i], xb + (uint32_t)((a_row + 16 * i) * 80 + 2 * kk + a_byt));
#pragma unroll
            for (int tp = 0; tp < 2; tp++)
                ldsm4(Bf[tp], wb + (uint32_t)((b_row + 16 * tp) * 80 + 2 * kk + b_byt));
#pragma unroll
            for (int i = 0; i < 4; i++)
#pragma unroll
                for (int j = 0; j < 4; j++)
                    mma_bf16(acc[i][j], A[i], &Bf[j >> 1][(j & 1) * 2]);
        }
    }

    // Epilogue
    const int q = lane & 3, g = lane >> 2;
#pragma unroll
    for (int i = 0; i < 4; i++) {
#pragma unroll
        for (int j = 0; j < 4; j++) {
            const int row0 = m0 + wm + 16 * i + g;
            const int col  = n0 + wn + 8 * j + 2 * q;
            float2 bi = *(const float2*)&bias[col];
            float a0 = (acc[i][j][0] + bi.x) * oscale, a1 = (acc[i][j][1] + bi.y) * oscale;
            float a2 = (acc[i][j][2] + bi.x) * oscale, a3 = (acc[i][j][3] + bi.y) * oscale;
            if (RES) {
                float2 r0 = *(const float2*)&R[(size_t)row0 * DMODEL + col];
                float2 r1 = *(const float2*)&R[(size_t)(row0 + 8) * DMODEL + col];
                a0 += r0.x; a1 += r0.y; a2 += r1.x; a3 += r1.y;
            }
            if (CBF) {
                __nv_bfloat16* Cb = (__nv_bfloat16*)Cv;
                *(uint32_t*)&Cb[(size_t)row0 * DMODEL + col]       = packbf(a0, a1);
                *(uint32_t*)&Cb[(size_t)(row0 + 8) * DMODEL + col] = packbf(a2, a3);
            } else {
                float* Cf = (float*)Cv;
                float2 o0; o0.x = a0; o0.y = a1;
                float2 o1; o1.x = a2; o1.y = a3;
                *(float2*)&Cf[(size_t)row0 * DMODEL + col]       = o0;
                *(float2*)&Cf[(size_t)(row0 + 8) * DMODEL + col] = o1;
            }
        }
    }
}

// Batched QKV projection; Q output pre-scaled by QSCALE.
__global__ __launch_bounds__(256, 2)
void gemm_qkv_bf16(const __nv_bfloat16* __restrict__ xq, const __nv_bfloat16* __restrict__ xk,
                   const __nv_bfloat16* __restrict__ xv,
                   const __nv_bfloat16* __restrict__ Wq, const __nv_bfloat16* __restrict__ Wk,
                   const __nv_bfloat16* __restrict__ Wv,
                   const float* __restrict__ bq, const float* __restrict__ bk,
                   const float* __restrict__ bv,
                   __nv_bfloat16* __restrict__ qp, __nv_bfloat16* __restrict__ kp,
                   __nv_bfloat16* __restrict__ vp)
{
    const __nv_bfloat16 *X, *W;
    const float* b;
    __nv_bfloat16* C;
    float sc;
    if (blockIdx.z == 0)      { X = xq; W = Wq; b = bq; C = qp; sc = QSCALE; }
    else if (blockIdx.z == 1) { X = xk; W = Wk; b = bk; C = kp; sc = 1.f; }
    else                      { X = xv; W = Wv; b = bv; C = vp; sc = 1.f; }
    gemm_body<false, true>(X, W, b, nullptr, C, blockIdx.y * 128, blockIdx.x * 128, sc);
}

// O projection (bf16 in -> fp32 out) with fp32 residual add.
__global__ __launch_bounds__(256, 2)
void gemm_o_bf16(const __nv_bfloat16* __restrict__ X, const __nv_bfloat16* __restrict__ W,
                 const float* __restrict__ bias, const float* __restrict__ R,
                 float* __restrict__ C)
{
    gemm_body<true, false>(X, W, bias, R, C, blockIdx.y * 128, blockIdx.x * 128, 1.f);
}

// ---------------------------------------------------------------------------
// BF16 flash attention; 3-stage cp.async K/V ring, ONE barrier per key tile.
// Q pre-scaled by 1/8*log2e -> bare ex2 softmax. Deferred l-reduction:
// each lane keeps a partial denominator; cross-lane sum happens once in
// the epilogue (removes 4 shfl chains per main-loop iteration).
// Block: q-tile 128, key tiles of 64, 8 warps (16 q rows each).
// ---------------------------------------------------------------------------
__global__ __launch_bounds__(256)
void attn_bf16(const __nv_bfloat16* __restrict__ Qp,
               const __nv_bfloat16* __restrict__ Kp,
               const __nv_bfloat16* __restrict__ Vp,
               __nv_bfloat16* __restrict__ Ctx)
{
    extern __shared__ __nv_bfloat16 smdyn[];
    __nv_bfloat16* Qs = smdyn;               // 128*72
    __nv_bfloat16* Ks = Qs + 128 * 72;       // 3 stages * 64*72
    __nv_bfloat16* Vs = Ks + 3 * 64 * 72;    // 3 stages * 64*72

    const int tid  = threadIdx.x;
    const int lane = tid & 31;
    const int wid  = tid >> 5;
    const int bh   = blockIdx.y;
    const int q0   = blockIdx.x * 128;
    const size_t base = (size_t)bh * SEQ * DKH;

    const int q = lane & 3, g = lane >> 2;

    const int a_row = 16 * wid + (lane & 15);
    const int a_byt = 16 * (lane >> 4);
    const int k_row = 8 * (lane >> 4) + (lane & 7);
    const int k_byt = 16 * ((lane >> 3) & 1);
    const int v_row = 8 * ((lane >> 3) & 1) + (lane & 7);
    const int v_byt = 16 * (lane >> 4);

    const uint32_t qs_b = (uint32_t)__cvta_generic_to_shared(Qs);
    const uint32_t ks_b = (uint32_t)__cvta_generic_to_shared(Ks);
    const uint32_t vs_b = (uint32_t)__cvta_generic_to_shared(Vs);

    const int c_row0 = tid >> 3;
    const int c_col0 = (tid & 7) * 16;

    auto stage_kv = [&](int kt, int buf) {
        const __nv_bfloat16* Kg = Kp + base + (size_t)(kt * 64) * DKH;
        const __nv_bfloat16* Vg = Vp + base + (size_t)(kt * 64) * DKH;
        const uint32_t kb = ks_b + (uint32_t)(buf * 64 * 144);
        const uint32_t vb = vs_b + (uint32_t)(buf * 64 * 144);
#pragma unroll
        for (int it = 0; it < 2; it++) {
            const int row = c_row0 + it * 32;
            cpasync16(kb + (uint32_t)(row * 144 + c_col0),
                      (const char*)Kg + (size_t)row * 128 + c_col0);
            cpasync16(vb + (uint32_t)(row * 144 + c_col0),
                      (const char*)Vg + (size_t)row * 128 + c_col0);
        }
    };

    // Prologue: Q + KV0 (group 0), KV1 (group 1)
    {
        const __nv_bfloat16* Qg = Qp + base + (size_t)q0 * DKH;
#pragma unroll
        for (int it = 0; it < 4; it++) {
            const int row = c_row0 + it * 32;
            cpasync16(qs_b + (uint32_t)(row * 144 + c_col0),
                      (const char*)Qg + (size_t)row * 128 + c_col0);
        }
        stage_kv(0, 0);
        CP_COMMIT();
        stage_kv(1, 1);
        CP_COMMIT();
    }

    float m0r = -INFINITY, m1r = -INFINITY;
    float l0p = 0.f, l1p = 0.f;     // lane-partial denominators
    float o[8][4];
#pragma unroll
    for (int j = 0; j < 8; j++)
#pragma unroll
        for (int c = 0; c < 4; c++) o[j][c] = 0.f;

    const int NT = SEQ / 64;   // 32
    for (int kt = 0; kt < NT; kt++) {
        const int cur = kt % 3;
        if (kt + 1 < NT) { CP_WAIT(1); } else { CP_WAIT(0); }
        __syncthreads();                      // all warps done with buf (kt-1)%3
        if (kt + 2 < NT) {                    // prefetch overlaps compute of kt
            stage_kv(kt + 2, (kt + 2) % 3);
            CP_COMMIT();
        }

        const uint32_t kcur = ks_b + (uint32_t)(cur * 64 * 144);
        const uint32_t vcur = vs_b + (uint32_t)(cur * 64 * 144);

        // --- Scores (already in exp2 domain thanks to Q pre-scale) ---
        float s[8][4];
#pragma unroll
        for (int j = 0; j < 8; j++)
#pragma unroll
            for (int c = 0; c < 4; c++) s[j][c] = 0.f;

#pragma unroll
        for (int kk = 0; kk < 64; kk += 16) {
            uint32_t A[4], Bf[4][4];
            ldsm4(A, qs_b + (uint32_t)(a_row * 144 + 2 * kk + a_byt));
#pragma unroll
            for (int tp = 0; tp < 4; tp++)
                ldsm4(Bf[tp], kcur + (uint32_t)((k_row + 16 * tp) * 144 + 2 * kk + k_byt));
#pragma unroll
            for (int j = 0; j < 8; j++)
                mma_bf16(s[j], A, &Bf[j >> 1][(j & 1) * 2]);
        }

        // --- Online softmax with ex2; only the MAX is shuffle-reduced ---
        float mx0 = s[0][0], mx1 = s[0][2];
#pragma unroll
        for (int j = 0; j < 8; j++) {
            mx0 = fmaxf(mx0, fmaxf(s[j][0], s[j][1]));
            mx1 = fmaxf(mx1, fmaxf(s[j][2], s[j][3]));
        }
        mx0 = fmaxf(mx0, __shfl_xor_sync(0xffffffffu, mx0, 1));
        mx0 = fmaxf(mx0, __shfl_xor_sync(0xffffffffu, mx0, 2));
        mx1 = fmaxf(mx1, __shfl_xor_sync(0xffffffffu, mx1, 1));
        mx1 = fmaxf(mx1, __shfl_xor_sync(0xffffffffu, mx1, 2));
        const float mn0 = fmaxf(m0r, mx0), mn1 = fmaxf(m1r, mx1);
        const float al0 = ex2(m0r - mn0), al1 = ex2(m1r - mn1);

        float sum0 = 0.f, sum1 = 0.f;
#pragma unroll
        for (int j = 0; j < 8; j++) {
            s[j][0] = ex2(s[j][0] - mn0);
            s[j][1] = ex2(s[j][1] - mn0);
            s[j][2] = ex2(s[j][2] - mn1);
            s[j][3] = ex2(s[j][3] - mn1);
            sum0 += s[j][0] + s[j][1];
            sum1 += s[j][2] + s[j][3];
        }
        // Lane-partial denominator update (alpha is lane-uniform per row).
        l0p = l0p * al0 + sum0;
        l1p = l1p * al1 + sum1;
        m0r = mn0; m1r = mn1;

#pragma unroll
        for (int j = 0; j < 8; j++) {
            o[j][0] *= al0; o[j][1] *= al0;
            o[j][2] *= al1; o[j][3] *= al1;
        }

        // --- Pack P accumulator fragments into PV A fragments (registers) ---
        uint32_t pA[4][4];
#pragma unroll
        for (int kc = 0; kc < 4; kc++) {
            pA[kc][0] = packbf(s[2 * kc][0],     s[2 * kc][1]);
            pA[kc][1] = packbf(s[2 * kc][2],     s[2 * kc][3]);
            pA[kc][2] = packbf(s[2 * kc + 1][0], s[2 * kc + 1][1]);
            pA[kc][3] = packbf(s[2 * kc + 1][2], s[2 * kc + 1][3]);
        }

        // --- ctx += P · V ---
#pragma unroll
        for (int kc = 0; kc < 4; kc++) {
#pragma unroll
            for (int jp = 0; jp < 4; jp++) {
                uint32_t Vf[4];
                ldsm4t(Vf, vcur + (uint32_t)((16 * kc + v_row) * 144 + 32 * jp + v_byt));
                mma_bf16(o[2 * jp],     pA[kc], &Vf[0]);
                mma_bf16(o[2 * jp + 1], pA[kc], &Vf[2]);
            }
        }
    }

    // Epilogue: cross-lane reduce the deferred denominators, normalize, store.
    float l0 = l0p, l1 = l1p;
    l0 += __shfl_xor_sync(0xffffffffu, l0, 1);
    l0 += __shfl_xor_sync(0xffffffffu, l0, 2);
    l1 += __shfl_xor_sync(0xffffffffu, l1, 1);
    l1 += __shfl_xor_sync(0xffffffffu, l1, 2);
    const float inv0 = 1.f / l0, inv1 = 1.f / l1;
    const int row0 = q0 + 16 * wid + g;
#pragma unroll
    for (int j = 0; j < 8; j++) {
        uint32_t u0 = packbf(o[j][0] * inv0, o[j][1] * inv0);
        uint32_t u1 = packbf(o[j][2] * inv1, o[j][3] * inv1);
        *(uint32_t*)&Ctx[base + (size_t)row0 * DKH + 8 * j + 2 * q]       = u0;
        *(uint32_t*)&Ctx[base + (size_t)(row0 + 8) * DKH + 8 * j + 2 * q] = u1;
    }
}

// ---------------------------------------------------------------------------
// In-place LayerNorm over last dim (1024). One block (256 thr) per row.
// ---------------------------------------------------------------------------
__global__ __launch_bounds__(256)
void layernorm_kernel(float* __restrict__ X, const float* __restrict__ gamma,
                      const float* __restrict__ beta)
{
    __shared__ float rs[8], rss[8];
    const int row = blockIdx.x;
    const int tid = threadIdx.x;

    float4 v = *(const float4*)&X[(size_t)row * DMODEL + tid * 4];
    float s  = v.x + v.y + v.z + v.w;
    float ss = v.x * v.x + v.y * v.y + v.z * v.z + v.w * v.w;

#pragma unroll
    for (int o = 16; o > 0; o >>= 1) {
        s  += __shfl_down_sync(0xffffffffu, s,  o);
        ss += __shfl_down_sync(0xffffffffu, ss, o);
    }
    const int w  = tid >> 5;
    const int ln = tid & 31;
    if (ln == 0) { rs[w] = s; rss[w] = ss; }
    __syncthreads();

    float tot = 0.f, tot2 = 0.f;
#pragma unroll
    for (int i = 0; i < 8; i++) { tot += rs[i]; tot2 += rss[i]; }
    const float mean = tot * (1.f / DMODEL);
    const float var  = tot2 * (1.f / DMODEL) - mean * mean;
    const float rstd = rsqrtf(var + 1e-6f);

    float4 g4 = *(const float4*)&gamma[tid * 4];
    float4 b4 = *(const float4*)&beta[tid * 4];
    float4 o;
    o.x = (v.x - mean) * rstd * g4.x + b4.x;
    o.y = (v.y - mean) * rstd * g4.y + b4.y;
    o.z = (v.z - mean) * rstd * g4.z + b4.z;
    o.w = (v.w - mean) * rstd * g4.w + b4.w;
    *(float4*)&X[(size_t)row * DMODEL + tid * 4] = o;
}

// ---------------------------------------------------------------------------
// Launch
// ---------------------------------------------------------------------------
extern "C" void kernel_launch(void* const* d_in, const int* in_sizes, int n_in,
                              void* d_out, int out_size)
{
    (void)in_sizes; (void)n_in; (void)out_size;
    const float* q     = (const float*)d_in[0];
    const float* k     = (const float*)d_in[1];
    const float* v     = (const float*)d_in[2];
    const float* Wq    = (const float*)d_in[3];
    const float* bq    = (const float*)d_in[4];
    const float* Wk    = (const float*)d_in[5];
    const float* bk    = (const float*)d_in[6];
    const float* Wv    = (const float*)d_in[7];
    const float* bv    = (const float*)d_in[8];
    const float* Wo    = (const float*)d_in[9];
    const float* bo    = (const float*)d_in[10];
    const float* gamma = (const float*)d_in[11];
    const float* beta  = (const float*)d_in[12];
    float* out = (float*)d_out;

    __nv_bfloat16 *qp, *kp, *vp, *ctx, *qin, *kin, *vin, *wq, *wk, *wv, *wo;
    cudaGetSymbolAddress((void**)&qp,  g_qp);
    cudaGetSymbolAddress((void**)&kp,  g_kp);
    cudaGetSymbolAddress((void**)&vp,  g_vp);
    cudaGetSymbolAddress((void**)&ctx, g_ctx);
    cudaGetSymbolAddress((void**)&qin, g_qin);
    cudaGetSymbolAddress((void**)&kin, g_kin);
    cudaGetSymbolAddress((void**)&vin, g_vin);
    cudaGetSymbolAddress((void**)&wq,  g_wq);
    cudaGetSymbolAddress((void**)&wk,  g_wk);
    cudaGetSymbolAddress((void**)&wv,  g_wv);
    cudaGetSymbolAddress((void**)&wo,  g_wo);

    static int smem_set = 0;
    const int attn_smem = (128 * 72 + 6 * 64 * 72) * 2;   // Q + 3*(K+V)
    if (!smem_set) {
        cudaFuncSetAttribute(attn_bf16, cudaFuncAttributeMaxDynamicSharedMemorySize, attn_smem);
        smem_set = 1;
    }

    dim3 gCvtIn(MTOK * DMODEL / 4 / 256, 3);    // (8192, 3)
    cvt_inputs<<<gCvtIn, 256>>>(q, k, v, qin, kin, vin);
    dim3 gCvtW(DMODEL * DMODEL / 4 / 256, 4);   // (1024, 4)
    cvt_weights<<<gCvtW, 256>>>(Wq, Wk, Wv, Wo, wq, wk, wv, wo);

    dim3 gQKV(DMODEL / 128, MTOK / 128, 3);     // (8, 64, 3)
    gemm_qkv_bf16<<<gQKV, 256>>>(qin, kin, vin, wq, wk, wv, bq, bk, bv, qp, kp, vp);

    dim3 gAttn(SEQ / 128, BHEADS);              // (16, 64)
    attn_bf16<<<gAttn, 256, attn_smem>>>(qp, kp, vp, ctx);

    dim3 gGemm(DMODEL / 128, MTOK / 128);       // (8, 64)
    gemm_o_bf16<<<gGemm, 256>>>(ctx, wo, bo, q, out);

    layernorm_kernel<<<MTOK, 256>>>(out, gamma, beta);
}